// round 12
// baseline (speedup 1.0000x reference)
#include <cuda_runtime.h>
#include <cuda_bf16.h>

// MultiBoxLoss (SSD), fully fused: one CTA per batch row.
// Stream row (coalesced float4 smem staging, __ldcs, next-chunk prefetch) ->
// per-anchor CE kept in registers -> block-parallel 3-level radix select of
// the k-th largest negative CE (validated; bisection fallback) -> per-row sum
// -> last CTA reduces 128 rows and writes the scalar (resets done counter).

#define ROWS 128
#define AA   8732
#define CC   21
#define CPR  273            // chunks of 32 anchors: 272 full + 1 of 28
#define NT   1024
#define PER  9              // chunks per warp (warps 0..16: 9, 17..31: 8)

__device__ double   g_rowsum[ROWS];
__device__ int      g_rowpos[ROWS];
__device__ unsigned g_done = 0u;   // reset by the finalizing block each run

// Warp-aggregated smem histogram add.
__device__ __forceinline__ void hist_add(unsigned* h, unsigned bin, unsigned mask)
{
    const unsigned peers  = __match_any_sync(mask, bin);
    const unsigned leader = __ffs(peers) - 1u;
    if ((threadIdx.x & 31u) == leader)
        atomicAdd(&h[bin], __popc(peers));
}

// Block-wide inclusive prefix sum over 1024 values (one per thread).
// Contains 2 __syncthreads. s_w must hold 32 unsigneds.
__device__ __forceinline__ unsigned block_scan_incl(
    unsigned v, unsigned* s_w, int wid, unsigned lane)
{
    #pragma unroll
    for (int off = 1; off < 32; off <<= 1) {
        const unsigned x = __shfl_up_sync(0xFFFFFFFFu, v, off);
        if (lane >= off) v += x;
    }
    if (lane == 31) s_w[wid] = v;
    __syncthreads();
    if (wid == 0) {
        unsigned t = s_w[lane];
        #pragma unroll
        for (int off = 1; off < 32; off <<= 1) {
            const unsigned x = __shfl_up_sync(0xFFFFFFFFu, t, off);
            if (lane >= off) t += x;
        }
        s_w[lane] = t;  // inclusive warp totals
    }
    __syncthreads();
    if (wid > 0) v += s_w[wid - 1];
    return v;
}

extern __shared__ float dynbuf[];   // 32 warps * 672 floats = 86016 B

__global__ __launch_bounds__(NT, 1) void mbl_fused(
    const float* __restrict__ conf,
    const float* __restrict__ loc,
    const int*   __restrict__ lab,
    const float* __restrict__ gloc,
    float* __restrict__ out)
{
    const int b    = blockIdx.x;
    const int tid  = threadIdx.x;
    const int wid  = tid >> 5;
    const unsigned lane = tid & 31u;

    __shared__ unsigned s_hist[2048];
    __shared__ unsigned s_w[32];
    __shared__ int      s_selbin;
    __shared__ unsigned s_selrank;
    __shared__ int      s_pos;
    __shared__ double   s_psum;
    __shared__ float    s_fsum;
    __shared__ unsigned s_cgt;
    __shared__ unsigned s_vgt, s_vge;
    __shared__ int      s_last;
    __shared__ double   s_d[4];
    __shared__ int      s_i[4];

    if (tid == 0) {
        s_pos = 0; s_psum = 0.0; s_fsum = 0.f; s_cgt = 0u;
        s_vgt = 0u; s_vge = 0u; s_last = 0;
    }

    float* sw = dynbuf + wid * 672;
    const size_t rowbase = (size_t)b * AA;

    float ce_reg[PER];
    float psum   = 0.f;
    int   poscnt = 0;

    // Prologue: load chunk (wid) — always a full 32-anchor chunk (wid < 272).
    float4 q[6];
    {
        const float4* src = (const float4*)(conf + (rowbase + (size_t)wid * 32) * CC);
        #pragma unroll
        for (int t = 0; t < 6; t++) {
            const int e = (int)lane + 32 * t;
            if (e < 168) q[t] = __ldcs(src + e);
        }
    }

    #pragma unroll
    for (int i = 0; i < PER; i++) {
        ce_reg[i] = 0.f;
        const int ch = wid + 32 * i;
        if (ch < CPR) {
            const int na = (ch == CPR - 1) ? (AA - (CPR - 1) * 32) : 32;  // 28 or 32
            const int n4 = (na * CC) >> 2;
            const size_t abase = rowbase + (size_t)ch * 32;

            // Store staged chunk to smem.
            #pragma unroll
            for (int t = 0; t < 6; t++) {
                const int e = (int)lane + 32 * t;
                if (e < n4) ((float4*)sw)[e] = q[t];
            }
            __syncwarp();

            // Prefetch next chunk while computing this one.
            const int chn = ch + 32;
            if (i + 1 < PER && chn < CPR) {
                const int n4n = (((chn == CPR - 1) ? (AA - (CPR - 1) * 32) : 32) * CC) >> 2;
                const float4* srcn = (const float4*)(conf + (rowbase + (size_t)chn * 32) * CC);
                #pragma unroll
                for (int t = 0; t < 6; t++) {
                    const int e = (int)lane + 32 * t;
                    if (e < n4n) q[t] = __ldcs(srcn + e);
                }
            }

            if ((int)lane < na) {
                const size_t idx = abase + (size_t)lane;
                const int lb = __ldg(lab + idx);
                const float* vp = sw + lane * CC;
                float m = vp[0];
                #pragma unroll
                for (int t2 = 1; t2 < CC; t2++) m = fmaxf(m, vp[t2]);
                float s = 0.f;
                #pragma unroll
                for (int t2 = 0; t2 < CC; t2++) s += __expf(vp[t2] - m);
                const float ce = m + __logf(s) - vp[lb];

                if (lb > 0) {
                    poscnt++;
                    float p = ce;
                    const float4 l4 = __ldg((const float4*)loc  + idx);
                    const float4 g4 = __ldg((const float4*)gloc + idx);
                    float d, ad;
                    d = l4.x - g4.x; ad = fabsf(d); p += (ad < 1.f) ? 0.5f * d * d : ad - 0.5f;
                    d = l4.y - g4.y; ad = fabsf(d); p += (ad < 1.f) ? 0.5f * d * d : ad - 0.5f;
                    d = l4.z - g4.z; ad = fabsf(d); p += (ad < 1.f) ? 0.5f * d * d : ad - 0.5f;
                    d = l4.w - g4.w; ad = fabsf(d); p += (ad < 1.f) ? 0.5f * d * d : ad - 0.5f;
                    psum += p;
                } else {
                    ce_reg[i] = ce;   // strictly > 0 for finite logits
                }
            }
            __syncwarp();
        }
    }

    unsigned bits[PER];
    #pragma unroll
    for (int i = 0; i < PER; i++) bits[i] = __float_as_uint(ce_reg[i]);

    // Zero level-1 histogram (2048 bins); barrier also publishes scalar inits.
    s_hist[tid] = 0u;
    s_hist[tid + 1024] = 0u;
    __syncthreads();

    // Pos/psum block reduction and level-1 histogram share one barrier pair.
    {
        int   pc = (int)__reduce_add_sync(0xFFFFFFFFu, (unsigned)poscnt);
        float ps = psum;
        #pragma unroll
        for (int off = 16; off; off >>= 1)
            ps += __shfl_down_sync(0xFFFFFFFFu, ps, off);
        if (lane == 0) {
            atomicAdd(&s_pos, pc);
            atomicAdd(&s_psum, (double)ps);
        }
    }
    #pragma unroll
    for (int i = 0; i < PER; i++)
        hist_add(s_hist, bits[i] >> 20, 0xFFFFFFFFu);
    __syncthreads();

    const int npos = s_pos;
    const int k = min(3 * npos, AA - npos);   // uniform across block

    double negsum = 0.0;
    if (k > 0) {
        unsigned r = (unsigned)k;

        // ---- Level 1: bits[30:20], 2048 bins (2 per thread, pair scan) ----
        {
            const int p = 1023 - tid;               // pair index, tid0 = topmost
            const unsigned h_hi = s_hist[2 * p + 1];
            const unsigned h_lo = s_hist[2 * p];
            const unsigned P = h_hi + h_lo;
            const unsigned cum = block_scan_incl(P, s_w, wid, lane);
            const unsigned above = cum - P;         // count strictly above pair
            if (cum >= r && above < r) {
                if (above + h_hi >= r) { s_selbin = 2 * p + 1; s_selrank = r - above; }
                else                   { s_selbin = 2 * p;     s_selrank = r - above - h_hi; }
            }
        }
        __syncthreads();
        const unsigned B1 = (unsigned)s_selbin;
        r = s_selrank;
        __syncthreads();

        // ---- Level 2: bits[19:10] among level-1 bin == B1 ----
        s_hist[tid] = 0u;
        __syncthreads();
        #pragma unroll
        for (int i = 0; i < PER; i++) {
            const bool act = ((bits[i] >> 20) == B1);
            const unsigned mask = __ballot_sync(0xFFFFFFFFu, act);
            if (act) hist_add(s_hist, (bits[i] >> 10) & 1023u, mask);
        }
        __syncthreads();
        {
            const int bin = 1023 - tid;
            const unsigned h = s_hist[bin];
            const unsigned cum = block_scan_incl(h, s_w, wid, lane);
            if (cum >= r && cum - h < r) { s_selbin = bin; s_selrank = r - (cum - h); }
        }
        __syncthreads();
        const unsigned top21 = (B1 << 10) | (unsigned)s_selbin;
        r = s_selrank;
        __syncthreads();

        // ---- Level 3: bits[9:0] among top-21-bit match ----
        s_hist[tid] = 0u;
        __syncthreads();
        #pragma unroll
        for (int i = 0; i < PER; i++) {
            const bool act = ((bits[i] >> 10) == top21);
            const unsigned mask = __ballot_sync(0xFFFFFFFFu, act);
            if (act) hist_add(s_hist, bits[i] & 1023u, mask);
        }
        __syncthreads();
        {
            const int bin = 1023 - tid;
            const unsigned h = s_hist[bin];
            const unsigned cum = block_scan_incl(h, s_w, wid, lane);
            if (cum >= r && cum - h < r) { s_selbin = bin; s_selrank = r - (cum - h); }
        }
        // Zero scratch for a possible bisection fallback.
        if (tid < 64) s_hist[tid + 1024] = 0u;
        __syncthreads();

        unsigned vbits = ((unsigned)top21 << 10) | (unsigned)s_selbin;

        // ---- Exact validation: count(>v) < k <= count(>=v) ----
        {
            unsigned cgt = 0u, cge = 0u;
            #pragma unroll
            for (int i = 0; i < PER; i++) {
                cgt += (bits[i] >  vbits) ? 1u : 0u;
                cge += (bits[i] >= vbits) ? 1u : 0u;
            }
            cgt = __reduce_add_sync(0xFFFFFFFFu, cgt);
            cge = __reduce_add_sync(0xFFFFFFFFu, cge);
            if (lane == 0) {
                atomicAdd(&s_vgt, cgt);
                atomicAdd(&s_vge, cge);
            }
        }
        __syncthreads();
        const bool valid = (s_vgt < (unsigned)k) && (s_vge >= (unsigned)k);

        if (!valid) {
            // ---- Fallback: bisection on float bits (known-correct) ----
            unsigned lo = 0u, hi = 0x7F800000u;
            int iter = 0;
            while (lo < hi) {
                const unsigned mid = (lo + hi) >> 1;
                unsigned c = 0;
                #pragma unroll
                for (int i = 0; i < PER; i++) c += (bits[i] > mid) ? 1u : 0u;
                c = __reduce_add_sync(0xFFFFFFFFu, c);
                if (lane == 0) atomicAdd(&s_hist[1024 + iter], c);
                __syncthreads();
                const unsigned tot = s_hist[1024 + iter];
                if (tot < (unsigned)k) hi = mid; else lo = mid + 1u;
                iter++;
            }
            vbits = lo;
        }

        const float vth = __uint_as_float(vbits);

        // Sum of values strictly greater + tie fill at threshold.
        float    fs  = 0.f;
        unsigned cgt = 0u;
        #pragma unroll
        for (int i = 0; i < PER; i++)
            if (bits[i] > vbits) { fs += ce_reg[i]; cgt++; }
        cgt = __reduce_add_sync(0xFFFFFFFFu, cgt);
        #pragma unroll
        for (int off = 16; off; off >>= 1)
            fs += __shfl_down_sync(0xFFFFFFFFu, fs, off);
        if (lane == 0) {
            atomicAdd(&s_fsum, fs);
            atomicAdd(&s_cgt, cgt);
        }
        __syncthreads();
        negsum = (double)s_fsum + (double)(k - (int)s_cgt) * (double)vth;
    }

    // Publish per-row result; last block finalizes and resets the counter.
    if (tid == 0) {
        g_rowsum[b] = s_psum + negsum;
        g_rowpos[b] = npos;
        __threadfence();
        if (atomicAdd(&g_done, 1u) == ROWS - 1) s_last = 1;
    }
    __syncthreads();
    if (s_last) {
        double rs = 0.0; int rp = 0;
        if (tid < ROWS) {
            rs = ((volatile double*)g_rowsum)[tid];
            rp = ((volatile int*)g_rowpos)[tid];
        }
        #pragma unroll
        for (int off = 16; off; off >>= 1) {
            rs += __shfl_down_sync(0xFFFFFFFFu, rs, off);
            rp += __shfl_down_sync(0xFFFFFFFFu, rp, off);
        }
        if (tid < ROWS && lane == 0) { s_d[wid] = rs; s_i[wid] = rp; }
        __syncthreads();
        if (tid == 0) {
            const double tot = s_d[0] + s_d[1] + s_d[2] + s_d[3];
            const int    np  = s_i[0] + s_i[1] + s_i[2] + s_i[3];
            out[0] = (float)(tot / (double)np);
            g_done = 0u;   // reset for the next graph replay
        }
    }
}

extern "C" void kernel_launch(void* const* d_in, const int* in_sizes, int n_in,
                              void* d_out, int out_size)
{
    const float* conf = (const float*)d_in[0];
    const float* loc  = (const float*)d_in[1];
    const int*   lab  = (const int*)  d_in[2];
    const float* gloc = (const float*)d_in[3];
    float* out = (float*)d_out;

    const int dyn = 32 * 672 * (int)sizeof(float);   // 86016 B
    cudaFuncSetAttribute(mbl_fused, cudaFuncAttributeMaxDynamicSharedMemorySize, dyn);
    mbl_fused<<<ROWS, NT, dyn>>>(conf, loc, lab, gloc, out);
}